// round 4
// baseline (speedup 1.0000x reference)
#include <cuda_runtime.h>
#include <stdint.h>

#define Nn 50000
#define Ee 250000
#define Hh 128
#define NH (Nn*Hh)
#define EPSf 1e-5f

// ---------------- device scratch (static, no allocs) ----------------
__device__ float g_h[NH];           // node features (reused h0 -> h -> h1 -> h2)
__device__ float g_xw[2*NH];        // xw per relation
__device__ float g_agg[2*NH];       // aggregation per relation
__device__ float g_pq[4*NH];        // Pb, Qb, Pc, Qc
__device__ float g_deg[2*Nn];
__device__ float g_dinv[2*Nn];
__device__ float g_stats[1024];     // [0:128)encSum [128:256)encSq [256:384)bSum [384:512)bSq [512:640)cSum [640:768)cSq
__device__ float g_encAC[2*Hh];     // a, c for encoder BN
__device__ float g_wp[2][Hh*2];     // folded BN*Wbp2 per relation
__device__ float g_bp[2][2];        // folded bias per relation
__device__ int   g_is64;

// ---------------- helpers ----------------
__device__ __forceinline__ long long ld_idx(const void* p, long long i, int is64) {
    return is64 ? ((const long long*)p)[i] : (long long)((const int*)p)[i];
}

// ---------------- kernels ----------------

// Detect whether edge indices are int64 (high 32-bit words of first 256 values all zero)
__global__ void k_detect(const int* w) {
    __shared__ int anynz;
    if (threadIdx.x == 0) anynz = 0;
    __syncthreads();
    if (w[threadIdx.x * 2 + 1] != 0) atomicExch(&anynz, 1);
    __syncthreads();
    if (threadIdx.x == 0) g_is64 = (anynz == 0) ? 1 : 0;
}

__global__ void k_zero() {
    int i = blockIdx.x * blockDim.x + threadIdx.x;
    if (i < 2 * Nn) g_deg[i] = 0.f;
    if (i < 1024) g_stats[i] = 0.f;
}

__global__ void k_deg(const void* __restrict__ beam, const void* __restrict__ col) {
    int t = blockIdx.x * blockDim.x + threadIdx.x;
    if (t >= 2 * Ee) return;
    int rel = (t >= Ee) ? 1 : 0;
    int e = t - rel * Ee;
    const void* ei = rel ? col : beam;
    long long d = ld_idx(ei, (long long)Ee + e, g_is64);
    atomicAdd(&g_deg[rel * Nn + d], 1.0f);
}

__global__ void k_dinv() {
    int i = blockIdx.x * blockDim.x + threadIdx.x;
    if (i < 2 * Nn) g_dinv[i] = rsqrtf(g_deg[i] + 1.0f);
}

// h0 = relu(x @ W_enc + b_enc) ; accumulate per-column sum/sumsq
__global__ void k_encoder(const float* __restrict__ x, const float* __restrict__ W,
                          const float* __restrict__ b) {
    int c = threadIdx.x;  // 0..127
    float w0 = W[c], w1 = W[Hh + c], w2 = W[2 * Hh + c], bb = b[c];
    float s = 0.f, s2 = 0.f;
    for (int n = blockIdx.x; n < Nn; n += gridDim.x) {
        float x0 = x[3 * n], x1 = x[3 * n + 1], x2 = x[3 * n + 2];
        float v = fmaxf(fmaf(x2, w2, fmaf(x1, w1, fmaf(x0, w0, bb))), 0.f);
        g_h[n * Hh + c] = v;
        s += v;
        s2 += v * v;
    }
    atomicAdd(&g_stats[c], s);
    atomicAdd(&g_stats[Hh + c], s2);
}

__global__ void k_bn_enc(const float* __restrict__ g, const float* __restrict__ be) {
    int c = threadIdx.x;
    float m = g_stats[c] * (1.0f / Nn);
    float v = g_stats[Hh + c] * (1.0f / Nn) - m * m;
    float a = g[c] * rsqrtf(v + EPSf);
    g_encAC[c] = a;
    g_encAC[Hh + c] = be[c] - a * m;
}

__global__ void k_bn_apply() {
    int i = blockIdx.x * blockDim.x + threadIdx.x;
    if (i >= Nn * 32) return;
    int c4 = i & 31;
    float4 a = ((const float4*)g_encAC)[c4];
    float4 cc = ((const float4*)(g_encAC + Hh))[c4];
    float4 h = ((float4*)g_h)[i];
    h.x = fmaf(a.x, h.x, cc.x);
    h.y = fmaf(a.y, h.y, cc.y);
    h.z = fmaf(a.z, h.z, cc.z);
    h.w = fmaf(a.w, h.w, cc.w);
    ((float4*)g_h)[i] = h;
}

// C[M,128] = A[M,128] @ B[128,128]  (row-major), fp32, 128x128 block / 8x8 thread tile
__global__ void __launch_bounds__(256) k_gemm(const float* __restrict__ A,
                                              const float* __restrict__ B,
                                              float* __restrict__ C, int M) {
    __shared__ float As[16][132];
    __shared__ float Bs[16][132];
    int m0 = blockIdx.x * 128;
    int tid = threadIdx.x;
    int tx = tid & 15, ty = tid >> 4;
    float acc[8][8];
#pragma unroll
    for (int i = 0; i < 8; i++)
#pragma unroll
        for (int j = 0; j < 8; j++) acc[i][j] = 0.f;

    for (int kk = 0; kk < 128; kk += 16) {
#pragma unroll
        for (int it = 0; it < 2; it++) {
            int idx = tid + it * 256;          // 0..511
            int r = idx >> 2;                  // 0..127
            int c4 = idx & 3;                  // 0..3
            int row = m0 + r;
            float4 v = make_float4(0.f, 0.f, 0.f, 0.f);
            if (row < M) v = *(const float4*)(A + (long long)row * 128 + kk + c4 * 4);
            As[c4 * 4 + 0][r] = v.x;
            As[c4 * 4 + 1][r] = v.y;
            As[c4 * 4 + 2][r] = v.z;
            As[c4 * 4 + 3][r] = v.w;
        }
#pragma unroll
        for (int it = 0; it < 2; it++) {
            int idx = tid + it * 256;
            int r = idx >> 5;                  // 0..15
            int c4 = idx & 31;                 // 0..31
            float4 v = *(const float4*)(B + (kk + r) * 128 + c4 * 4);
            *(float4*)(&Bs[r][c4 * 4]) = v;
        }
        __syncthreads();
#pragma unroll
        for (int k = 0; k < 16; k++) {
            float a[8], bfrag[8];
#pragma unroll
            for (int i = 0; i < 8; i++) a[i] = As[k][ty * 8 + i];
#pragma unroll
            for (int j = 0; j < 8; j++) bfrag[j] = Bs[k][tx * 8 + j];
#pragma unroll
            for (int i = 0; i < 8; i++)
#pragma unroll
                for (int j = 0; j < 8; j++) acc[i][j] = fmaf(a[i], bfrag[j], acc[i][j]);
        }
        __syncthreads();
    }
#pragma unroll
    for (int i = 0; i < 8; i++) {
        int row = m0 + ty * 8 + i;
        if (row < M) {
            float4* cp = (float4*)(C + (long long)row * 128 + tx * 8);
            cp[0] = make_float4(acc[i][0], acc[i][1], acc[i][2], acc[i][3]);
            cp[1] = make_float4(acc[i][4], acc[i][5], acc[i][6], acc[i][7]);
        }
    }
}

// agg[rel] = bias[rel] + dinv[rel]^2 * xw[rel]
__global__ void k_init_agg(const float* __restrict__ bb, const float* __restrict__ bc) {
    int i = blockIdx.x * blockDim.x + threadIdx.x;
    if (i >= Nn * 32) return;
    int n = i >> 5, c4 = i & 31;
    float d0 = g_dinv[n]; d0 *= d0;
    float d1 = g_dinv[Nn + n]; d1 *= d1;
    float4 biasb = ((const float4*)bb)[c4];
    float4 biasc = ((const float4*)bc)[c4];
    float4 x0 = ((const float4*)g_xw)[i];
    float4 x1 = ((const float4*)(g_xw + NH))[i];
    float4 r0, r1;
    r0.x = fmaf(d0, x0.x, biasb.x); r0.y = fmaf(d0, x0.y, biasb.y);
    r0.z = fmaf(d0, x0.z, biasb.z); r0.w = fmaf(d0, x0.w, biasb.w);
    r1.x = fmaf(d1, x1.x, biasc.x); r1.y = fmaf(d1, x1.y, biasc.y);
    r1.z = fmaf(d1, x1.z, biasc.z); r1.w = fmaf(d1, x1.w, biasc.w);
    ((float4*)g_agg)[i] = r0;
    ((float4*)(g_agg + NH))[i] = r1;
}

// per edge: agg[dst] += dinv[s]*dinv[d] * xw[src]   (one warp per edge, v4 red)
__global__ void k_scatter(const void* __restrict__ ei, const float* __restrict__ dinv,
                          const float* __restrict__ xw, float* __restrict__ agg) {
    int gt = blockIdx.x * blockDim.x + threadIdx.x;
    int e = gt >> 5;
    int lane = gt & 31;
    if (e >= Ee) return;
    int is64 = g_is64;
    long long s = ld_idx(ei, e, is64);
    long long d = ld_idx(ei, (long long)Ee + e, is64);
    float nrm = dinv[s] * dinv[d];
    float4 v = *(const float4*)(xw + s * Hh + lane * 4);
    float* p = agg + d * Hh + lane * 4;
    asm volatile("red.global.add.v4.f32 [%0], {%1,%2,%3,%4};" ::
                 "l"(p), "f"(v.x * nrm), "f"(v.y * nrm), "f"(v.z * nrm), "f"(v.w * nrm)
                 : "memory");
}

__global__ void k_combine(int dorelu) {
    int i = blockIdx.x * blockDim.x + threadIdx.x;
    if (i >= Nn * 32) return;
    float4 a = ((const float4*)g_agg)[i];
    float4 b = ((const float4*)(g_agg + NH))[i];
    float4 r;
    r.x = a.x + b.x; r.y = a.y + b.y; r.z = a.z + b.z; r.w = a.w + b.w;
    if (dorelu) {
        r.x = fmaxf(r.x, 0.f); r.y = fmaxf(r.y, 0.f);
        r.z = fmaxf(r.z, 0.f); r.w = fmaxf(r.w, 0.f);
    }
    ((float4*)g_h)[i] = r;
}

// pass A: z = relu(P[s] + Q[d] + bias); accumulate per-column sum/sumsq
__global__ void k_edge_stats(const void* __restrict__ ei, const float* __restrict__ P,
                             const float* __restrict__ Q, const float* __restrict__ bias,
                             float* __restrict__ sum, float* __restrict__ sq) {
    int lane = threadIdx.x & 31;
    int warp = (blockIdx.x * blockDim.x + threadIdx.x) >> 5;
    int nw = (gridDim.x * blockDim.x) >> 5;
    float4 b = ((const float4*)bias)[lane];
    float4 s = make_float4(0.f, 0.f, 0.f, 0.f);
    float4 s2 = make_float4(0.f, 0.f, 0.f, 0.f);
    int is64 = g_is64;
    for (int e = warp; e < Ee; e += nw) {
        long long si = ld_idx(ei, e, is64);
        long long di = ld_idx(ei, (long long)Ee + e, is64);
        float4 p = ((const float4*)P)[si * 32 + lane];
        float4 q = ((const float4*)Q)[di * 32 + lane];
        float4 z;
        z.x = fmaxf(p.x + q.x + b.x, 0.f);
        z.y = fmaxf(p.y + q.y + b.y, 0.f);
        z.z = fmaxf(p.z + q.z + b.z, 0.f);
        z.w = fmaxf(p.w + q.w + b.w, 0.f);
        s.x += z.x; s.y += z.y; s.z += z.z; s.w += z.w;
        s2.x += z.x * z.x; s2.y += z.y * z.y; s2.z += z.z * z.z; s2.w += z.w * z.w;
    }
    int c = lane * 4;
    atomicAdd(&sum[c + 0], s.x); atomicAdd(&sum[c + 1], s.y);
    atomicAdd(&sum[c + 2], s.z); atomicAdd(&sum[c + 3], s.w);
    atomicAdd(&sq[c + 0], s2.x); atomicAdd(&sq[c + 1], s2.y);
    atomicAdd(&sq[c + 2], s2.z); atomicAdd(&sq[c + 3], s2.w);
}

// fold BN into 128->2 projection: W' = a .* Wbp2 rows, b' = c @ Wbp2 + bbp2
__global__ void k_bn_pred(const float* gb, const float* beb, const float* W2b, const float* b2b,
                          const float* gc, const float* bec, const float* W2c, const float* b2c) {
    __shared__ float r0s[Hh], r1s[Hh];
    int k = threadIdx.x;
    for (int rel = 0; rel < 2; rel++) {
        const float* g  = rel ? gc  : gb;
        const float* be = rel ? bec : beb;
        const float* W2 = rel ? W2c : W2b;
        const float* b2 = rel ? b2c : b2b;
        const float* sum = &g_stats[256 + rel * 256];
        const float* sq  = &g_stats[256 + rel * 256 + 128];
        float m = sum[k] * (1.0f / Ee);
        float v = sq[k] * (1.0f / Ee) - m * m;
        float a = g[k] * rsqrtf(v + EPSf);
        float cc = be[k] - a * m;
        float w0 = W2[k * 2], w1 = W2[k * 2 + 1];
        g_wp[rel][k * 2] = a * w0;
        g_wp[rel][k * 2 + 1] = a * w1;
        r0s[k] = cc * w0;
        r1s[k] = cc * w1;
        __syncthreads();
        for (int off = 64; off > 0; off >>= 1) {
            if (k < off) { r0s[k] += r0s[k + off]; r1s[k] += r1s[k + off]; }
            __syncthreads();
        }
        if (k == 0) {
            g_bp[rel][0] = r0s[0] + b2[0];
            g_bp[rel][1] = r1s[0] + b2[1];
        }
        __syncthreads();
    }
}

// pass B: recompute z, project with folded weights, write [E,2]
__global__ void k_pred(const void* __restrict__ ei, const float* __restrict__ P,
                       const float* __restrict__ Q, const float* __restrict__ bias,
                       int rel, float* __restrict__ out) {
    int gt = blockIdx.x * blockDim.x + threadIdx.x;
    int e = gt >> 5;
    int lane = gt & 31;
    if (e >= Ee) return;
    int is64 = g_is64;
    float4 b = ((const float4*)bias)[lane];
    const float* W = g_wp[rel];
    float w00 = W[(4 * lane + 0) * 2], w01 = W[(4 * lane + 0) * 2 + 1];
    float w10 = W[(4 * lane + 1) * 2], w11 = W[(4 * lane + 1) * 2 + 1];
    float w20 = W[(4 * lane + 2) * 2], w21 = W[(4 * lane + 2) * 2 + 1];
    float w30 = W[(4 * lane + 3) * 2], w31 = W[(4 * lane + 3) * 2 + 1];
    long long si = ld_idx(ei, e, is64);
    long long di = ld_idx(ei, (long long)Ee + e, is64);
    float4 p = ((const float4*)P)[si * 32 + lane];
    float4 q = ((const float4*)Q)[di * 32 + lane];
    float4 z;
    z.x = fmaxf(p.x + q.x + b.x, 0.f);
    z.y = fmaxf(p.y + q.y + b.y, 0.f);
    z.z = fmaxf(p.z + q.z + b.z, 0.f);
    z.w = fmaxf(p.w + q.w + b.w, 0.f);
    float s0 = z.x * w00 + z.y * w10 + z.z * w20 + z.w * w30;
    float s1 = z.x * w01 + z.y * w11 + z.z * w21 + z.w * w31;
#pragma unroll
    for (int off = 16; off > 0; off >>= 1) {
        s0 += __shfl_xor_sync(0xffffffffu, s0, off);
        s1 += __shfl_xor_sync(0xffffffffu, s1, off);
    }
    if (lane == 0) {
        float2 r = make_float2(s0 + g_bp[rel][0], s1 + g_bp[rel][1]);
        ((float2*)out)[e] = r;
    }
}

__global__ void k_etypes(float* __restrict__ out) {
    int i = blockIdx.x * blockDim.x + threadIdx.x;
    if (i < 2 * Ee) out[i] = (i < Ee) ? 0.f : 1.f;
}

// ---------------- host ----------------
extern "C" void kernel_launch(void* const* d_in, const int* in_sizes, int n_in,
                              void* d_out, int out_size) {
    (void)in_sizes; (void)n_in; (void)out_size;
    const float* x     = (const float*)d_in[0];
    const void*  beam  = d_in[1];
    const void*  col   = d_in[2];
    const float* W_enc = (const float*)d_in[3];
    const float* b_enc = (const float*)d_in[4];
    const float* g_enc = (const float*)d_in[5];
    const float* be_enc= (const float*)d_in[6];
    const float* W1b   = (const float*)d_in[7];
    const float* b1b   = (const float*)d_in[8];
    const float* W1c   = (const float*)d_in[9];
    const float* b1c   = (const float*)d_in[10];
    const float* W2b   = (const float*)d_in[11];
    const float* b2b   = (const float*)d_in[12];
    const float* W2c   = (const float*)d_in[13];
    const float* b2c   = (const float*)d_in[14];
    const float* Wbp1  = (const float*)d_in[15];
    const float* bbp1  = (const float*)d_in[16];
    const float* gbp   = (const float*)d_in[17];
    const float* bebp  = (const float*)d_in[18];
    const float* Wbp2  = (const float*)d_in[19];
    const float* bbp2  = (const float*)d_in[20];
    const float* Wcp1  = (const float*)d_in[21];
    const float* bcp1  = (const float*)d_in[22];
    const float* gcp   = (const float*)d_in[23];
    const float* becp  = (const float*)d_in[24];
    const float* Wcp2  = (const float*)d_in[25];
    const float* bcp2  = (const float*)d_in[26];
    float* out = (float*)d_out;

    float *p_h, *p_xw, *p_agg, *p_pq, *p_dinv, *p_stats;
    cudaGetSymbolAddress((void**)&p_h, g_h);
    cudaGetSymbolAddress((void**)&p_xw, g_xw);
    cudaGetSymbolAddress((void**)&p_agg, g_agg);
    cudaGetSymbolAddress((void**)&p_pq, g_pq);
    cudaGetSymbolAddress((void**)&p_dinv, g_dinv);
    cudaGetSymbolAddress((void**)&p_stats, g_stats);

    const int GB = (Nn + 127) / 128;           // 391 gemm blocks
    const int NV4 = Nn * 32;                   // float4 elements per N*128 buffer
    const int EV = Ee * 32;                    // one warp per edge

    k_detect<<<1, 256>>>((const int*)beam);
    k_zero<<<(2 * Nn + 255) / 256, 256>>>();
    k_deg<<<(2 * Ee + 255) / 256, 256>>>(beam, col);
    k_dinv<<<(2 * Nn + 255) / 256, 256>>>();

    k_encoder<<<512, 128>>>(x, W_enc, b_enc);
    k_bn_enc<<<1, 128>>>(g_enc, be_enc);
    k_bn_apply<<<(NV4 + 255) / 256, 256>>>();

    // GCN layer 1
    k_gemm<<<GB, 256>>>(p_h, W1b, p_xw, Nn);
    k_gemm<<<GB, 256>>>(p_h, W1c, p_xw + NH, Nn);
    k_init_agg<<<(NV4 + 255) / 256, 256>>>(b1b, b1c);
    k_scatter<<<(EV + 255) / 256, 256>>>(beam, p_dinv, p_xw, p_agg);
    k_scatter<<<(EV + 255) / 256, 256>>>(col, p_dinv + Nn, p_xw + NH, p_agg + NH);
    k_combine<<<(NV4 + 255) / 256, 256>>>(1);

    // GCN layer 2
    k_gemm<<<GB, 256>>>(p_h, W2b, p_xw, Nn);
    k_gemm<<<GB, 256>>>(p_h, W2c, p_xw + NH, Nn);
    k_init_agg<<<(NV4 + 255) / 256, 256>>>(b2b, b2c);
    k_scatter<<<(EV + 255) / 256, 256>>>(beam, p_dinv, p_xw, p_agg);
    k_scatter<<<(EV + 255) / 256, 256>>>(col, p_dinv + Nn, p_xw + NH, p_agg + NH);
    k_combine<<<(NV4 + 255) / 256, 256>>>(0);

    // edge predictors: P/Q = h2 @ (top/bottom halves of Wbp1 / Wcp1)
    k_gemm<<<GB, 256>>>(p_h, Wbp1, p_pq, Nn);
    k_gemm<<<GB, 256>>>(p_h, Wbp1 + Hh * Hh, p_pq + NH, Nn);
    k_gemm<<<GB, 256>>>(p_h, Wcp1, p_pq + 2 * NH, Nn);
    k_gemm<<<GB, 256>>>(p_h, Wcp1 + Hh * Hh, p_pq + 3 * NH, Nn);

    k_edge_stats<<<512, 256>>>(beam, p_pq, p_pq + NH, bbp1, p_stats + 256, p_stats + 384);
    k_edge_stats<<<512, 256>>>(col, p_pq + 2 * NH, p_pq + 3 * NH, bcp1, p_stats + 512, p_stats + 640);
    k_bn_pred<<<1, 128>>>(gbp, bebp, Wbp2, bbp2, gcp, becp, Wcp2, bcp2);

    k_pred<<<(EV + 255) / 256, 256>>>(beam, p_pq, p_pq + NH, bbp1, 0, out);
    k_pred<<<(EV + 255) / 256, 256>>>(col, p_pq + 2 * NH, p_pq + 3 * NH, bcp1, 1, out + 2 * Ee);
    k_etypes<<<(2 * Ee + 255) / 256, 256>>>(out + 4 * Ee);
}

// round 7
// speedup vs baseline: 1.1142x; 1.1142x over previous
#include <cuda_runtime.h>
#include <stdint.h>

#define Nn 50000
#define Ee 250000
#define Hh 128
#define NH (Nn*Hh)
#define EPSf 1e-5f

// ---------------- device scratch (static, no allocs) ----------------
__device__ float g_h[NH];           // node features (h0 -> h -> h1 -> h2)
__device__ float g_xw[2*NH];        // xw per relation
__device__ float g_agg[2*NH];       // aggregation per relation
__device__ float g_pq[4*NH];        // Pb, Qb, Pc, Qc
__device__ float g_deg[2*Nn];
__device__ float g_dinv[2*Nn];
__device__ float g_stats[1024];
__device__ float g_encAC[2*Hh];
__device__ float g_wp[2][Hh*2];
__device__ float g_bp[2][2];
__device__ int   g_is64;

// ---------------- helpers ----------------
__device__ __forceinline__ long long ld_idx(const void* p, long long i, int is64) {
    return is64 ? ((const long long*)p)[i] : (long long)((const int*)p)[i];
}

// tf32 cvt: destination must be .b32
__device__ __forceinline__ uint32_t tf32_rna(float x) {
    uint32_t r;
    asm("cvt.rna.tf32.f32 %0, %1;" : "=r"(r) : "f"(x));
    return r;
}

__device__ __forceinline__ void mma_tf32(float* d, const uint32_t* a, const uint32_t* b) {
    asm volatile(
        "mma.sync.aligned.m16n8k8.row.col.f32.tf32.tf32.f32 "
        "{%0,%1,%2,%3}, {%4,%5,%6,%7}, {%8,%9}, {%0,%1,%2,%3};"
        : "+f"(d[0]), "+f"(d[1]), "+f"(d[2]), "+f"(d[3])
        : "r"(a[0]), "r"(a[1]), "r"(a[2]), "r"(a[3]), "r"(b[0]), "r"(b[1]));
}

// ---------------- mma.sync 3xTF32 GEMM ----------------
// C[y][M,128] = A[M,128] @ W[y][128,128]   (row-major)
// Block tile 128x128, 8 warps (4m x 2n), warp tile 32x64, K chunk 32.
#define APAD 36
#define BPAD 136
#define SMEM_MM ((128*APAD*2 + 32*BPAD*2) * 4)

__global__ void __launch_bounds__(256)
k_mma(const float* __restrict__ A,
      const float* __restrict__ W0, const float* __restrict__ W1,
      const float* __restrict__ W2, const float* __restrict__ W3,
      float* __restrict__ C0, float* __restrict__ C1,
      float* __restrict__ C2, float* __restrict__ C3, int M) {
    extern __shared__ uint32_t sm[];
    uint32_t* Ahi = sm;                       // [128][APAD]
    uint32_t* Alo = Ahi + 128 * APAD;
    uint32_t* Bhi = Alo + 128 * APAD;         // [32][BPAD]
    uint32_t* Blo = Bhi + 32 * BPAD;

    int tid = threadIdx.x;
    int lane = tid & 31, wid = tid >> 5;
    int wm = wid >> 1, wn = wid & 1;          // warp grid 4x2
    int m0 = blockIdx.x * 128;
    int qt = lane >> 2;                       // 0..7
    int qr = lane & 3;                        // 0..3

    const float* W = (blockIdx.y == 0) ? W0 : (blockIdx.y == 1) ? W1 : (blockIdx.y == 2) ? W2 : W3;
    float* C = (blockIdx.y == 0) ? C0 : (blockIdx.y == 1) ? C1 : (blockIdx.y == 2) ? C2 : C3;

    float acc[2][8][4];
#pragma unroll
    for (int i = 0; i < 2; i++)
#pragma unroll
        for (int j = 0; j < 8; j++)
#pragma unroll
            for (int q = 0; q < 4; q++) acc[i][j][q] = 0.f;

    for (int ch = 0; ch < 4; ch++) {
        int k0 = ch * 32;
        if (ch > 0) __syncthreads();
        // ---- fill A chunk [128 rows x 32 k] hi/lo ----
#pragma unroll
        for (int rep = 0; rep < 4; rep++) {
            int i4 = tid + rep * 256;         // 0..1023 float4s
            int r = i4 >> 3;                  // row 0..127
            int c = (i4 & 7) * 4;             // k 0..28
            float4 v = make_float4(0.f, 0.f, 0.f, 0.f);
            if (m0 + r < M) v = *(const float4*)(A + (size_t)(m0 + r) * 128 + k0 + c);
            uint4 h, l;
            h.x = tf32_rna(v.x); l.x = tf32_rna(v.x - __uint_as_float(h.x));
            h.y = tf32_rna(v.y); l.y = tf32_rna(v.y - __uint_as_float(h.y));
            h.z = tf32_rna(v.z); l.z = tf32_rna(v.z - __uint_as_float(h.z));
            h.w = tf32_rna(v.w); l.w = tf32_rna(v.w - __uint_as_float(h.w));
            *(uint4*)(Ahi + r * APAD + c) = h;
            *(uint4*)(Alo + r * APAD + c) = l;
        }
        // ---- fill B chunk: Bs[k][n] = W[(k0+k)*128 + n] ----
#pragma unroll
        for (int rep = 0; rep < 4; rep++) {
            int i4 = tid + rep * 256;
            int kk = i4 >> 5;                 // 0..31
            int n = (i4 & 31) * 4;            // 0..124
            float4 v = *(const float4*)(W + (size_t)(k0 + kk) * 128 + n);
            uint4 h, l;
            h.x = tf32_rna(v.x); l.x = tf32_rna(v.x - __uint_as_float(h.x));
            h.y = tf32_rna(v.y); l.y = tf32_rna(v.y - __uint_as_float(h.y));
            h.z = tf32_rna(v.z); l.z = tf32_rna(v.z - __uint_as_float(h.z));
            h.w = tf32_rna(v.w); l.w = tf32_rna(v.w - __uint_as_float(h.w));
            *(uint4*)(Bhi + kk * BPAD + n) = h;
            *(uint4*)(Blo + kk * BPAD + n) = l;
        }
        __syncthreads();
        // ---- compute 4 k-steps of 8 ----
#pragma unroll
        for (int s = 0; s < 4; s++) {
            int k = s * 8;
            uint32_t ah[2][4], al[2][4];
#pragma unroll
            for (int mf = 0; mf < 2; mf++) {
                int r0 = wm * 32 + mf * 16 + qt;
                int kc = k + qr;
                ah[mf][0] = Ahi[r0 * APAD + kc];
                ah[mf][1] = Ahi[(r0 + 8) * APAD + kc];
                ah[mf][2] = Ahi[r0 * APAD + kc + 4];
                ah[mf][3] = Ahi[(r0 + 8) * APAD + kc + 4];
                al[mf][0] = Alo[r0 * APAD + kc];
                al[mf][1] = Alo[(r0 + 8) * APAD + kc];
                al[mf][2] = Alo[r0 * APAD + kc + 4];
                al[mf][3] = Alo[(r0 + 8) * APAD + kc + 4];
            }
            uint32_t bh[8][2], bl[8][2];
#pragma unroll
            for (int nf = 0; nf < 8; nf++) {
                int cn = wn * 64 + nf * 8 + qt;
                int kr = k + qr;
                bh[nf][0] = Bhi[kr * BPAD + cn];
                bh[nf][1] = Bhi[(kr + 4) * BPAD + cn];
                bl[nf][0] = Blo[kr * BPAD + cn];
                bl[nf][1] = Blo[(kr + 4) * BPAD + cn];
            }
#pragma unroll
            for (int mf = 0; mf < 2; mf++)
#pragma unroll
                for (int nf = 0; nf < 8; nf++) {
                    mma_tf32(acc[mf][nf], ah[mf], bh[nf]);
                    mma_tf32(acc[mf][nf], ah[mf], bl[nf]);
                    mma_tf32(acc[mf][nf], al[mf], bh[nf]);
                }
        }
    }
    // ---- epilogue ----
#pragma unroll
    for (int mf = 0; mf < 2; mf++) {
        int r = m0 + wm * 32 + mf * 16 + qt;
#pragma unroll
        for (int nf = 0; nf < 8; nf++) {
            int cc = wn * 64 + nf * 8 + qr * 2;
            if (r < M)
                *(float2*)(C + (size_t)r * 128 + cc) = make_float2(acc[mf][nf][0], acc[mf][nf][1]);
            if (r + 8 < M)
                *(float2*)(C + (size_t)(r + 8) * 128 + cc) = make_float2(acc[mf][nf][2], acc[mf][nf][3]);
        }
    }
}

// ---------------- non-GEMM kernels (unchanged, verified R4) ----------------

__global__ void k_detect(const int* w) {
    __shared__ int anynz;
    if (threadIdx.x == 0) anynz = 0;
    __syncthreads();
    if (w[threadIdx.x * 2 + 1] != 0) atomicExch(&anynz, 1);
    __syncthreads();
    if (threadIdx.x == 0) g_is64 = (anynz == 0) ? 1 : 0;
}

__global__ void k_zero() {
    int i = blockIdx.x * blockDim.x + threadIdx.x;
    if (i < 2 * Nn) g_deg[i] = 0.f;
    if (i < 1024) g_stats[i] = 0.f;
}

__global__ void k_deg(const void* __restrict__ beam, const void* __restrict__ col) {
    int t = blockIdx.x * blockDim.x + threadIdx.x;
    if (t >= 2 * Ee) return;
    int rel = (t >= Ee) ? 1 : 0;
    int e = t - rel * Ee;
    const void* ei = rel ? col : beam;
    long long d = ld_idx(ei, (long long)Ee + e, g_is64);
    atomicAdd(&g_deg[rel * Nn + d], 1.0f);
}

__global__ void k_dinv() {
    int i = blockIdx.x * blockDim.x + threadIdx.x;
    if (i < 2 * Nn) g_dinv[i] = rsqrtf(g_deg[i] + 1.0f);
}

__global__ void k_encoder(const float* __restrict__ x, const float* __restrict__ W,
                          const float* __restrict__ b) {
    int c = threadIdx.x;
    float w0 = W[c], w1 = W[Hh + c], w2 = W[2 * Hh + c], bb = b[c];
    float s = 0.f, s2 = 0.f;
    for (int n = blockIdx.x; n < Nn; n += gridDim.x) {
        float x0 = x[3 * n], x1 = x[3 * n + 1], x2 = x[3 * n + 2];
        float v = fmaxf(fmaf(x2, w2, fmaf(x1, w1, fmaf(x0, w0, bb))), 0.f);
        g_h[n * Hh + c] = v;
        s += v; s2 += v * v;
    }
    atomicAdd(&g_stats[c], s);
    atomicAdd(&g_stats[Hh + c], s2);
}

__global__ void k_bn_enc(const float* __restrict__ g, const float* __restrict__ be) {
    int c = threadIdx.x;
    float m = g_stats[c] * (1.0f / Nn);
    float v = g_stats[Hh + c] * (1.0f / Nn) - m * m;
    float a = g[c] * rsqrtf(v + EPSf);
    g_encAC[c] = a;
    g_encAC[Hh + c] = be[c] - a * m;
}

__global__ void k_bn_apply() {
    int i = blockIdx.x * blockDim.x + threadIdx.x;
    if (i >= Nn * 32) return;
    int c4 = i & 31;
    float4 a = ((const float4*)g_encAC)[c4];
    float4 cc = ((const float4*)(g_encAC + Hh))[c4];
    float4 h = ((float4*)g_h)[i];
    h.x = fmaf(a.x, h.x, cc.x);
    h.y = fmaf(a.y, h.y, cc.y);
    h.z = fmaf(a.z, h.z, cc.z);
    h.w = fmaf(a.w, h.w, cc.w);
    ((float4*)g_h)[i] = h;
}

__global__ void k_init_agg(const float* __restrict__ bb, const float* __restrict__ bc) {
    int i = blockIdx.x * blockDim.x + threadIdx.x;
    if (i >= Nn * 32) return;
    int n = i >> 5, c4 = i & 31;
    float d0 = g_dinv[n]; d0 *= d0;
    float d1 = g_dinv[Nn + n]; d1 *= d1;
    float4 biasb = ((const float4*)bb)[c4];
    float4 biasc = ((const float4*)bc)[c4];
    float4 x0 = ((const float4*)g_xw)[i];
    float4 x1 = ((const float4*)(g_xw + NH))[i];
    float4 r0, r1;
    r0.x = fmaf(d0, x0.x, biasb.x); r0.y = fmaf(d0, x0.y, biasb.y);
    r0.z = fmaf(d0, x0.z, biasb.z); r0.w = fmaf(d0, x0.w, biasb.w);
    r1.x = fmaf(d1, x1.x, biasc.x); r1.y = fmaf(d1, x1.y, biasc.y);
    r1.z = fmaf(d1, x1.z, biasc.z); r1.w = fmaf(d1, x1.w, biasc.w);
    ((float4*)g_agg)[i] = r0;
    ((float4*)(g_agg + NH))[i] = r1;
}

__global__ void k_scatter(const void* __restrict__ ei, const float* __restrict__ dinv,
                          const float* __restrict__ xw, float* __restrict__ agg) {
    int gt = blockIdx.x * blockDim.x + threadIdx.x;
    int e = gt >> 5;
    int lane = gt & 31;
    if (e >= Ee) return;
    int is64 = g_is64;
    long long s = ld_idx(ei, e, is64);
    long long d = ld_idx(ei, (long long)Ee + e, is64);
    float nrm = dinv[s] * dinv[d];
    float4 v = *(const float4*)(xw + s * Hh + lane * 4);
    float* p = agg + d * Hh + lane * 4;
    asm volatile("red.global.add.v4.f32 [%0], {%1,%2,%3,%4};" ::
                 "l"(p), "f"(v.x * nrm), "f"(v.y * nrm), "f"(v.z * nrm), "f"(v.w * nrm)
                 : "memory");
}

__global__ void k_combine(int dorelu) {
    int i = blockIdx.x * blockDim.x + threadIdx.x;
    if (i >= Nn * 32) return;
    float4 a = ((const float4*)g_agg)[i];
    float4 b = ((const float4*)(g_agg + NH))[i];
    float4 r;
    r.x = a.x + b.x; r.y = a.y + b.y; r.z = a.z + b.z; r.w = a.w + b.w;
    if (dorelu) {
        r.x = fmaxf(r.x, 0.f); r.y = fmaxf(r.y, 0.f);
        r.z = fmaxf(r.z, 0.f); r.w = fmaxf(r.w, 0.f);
    }
    ((float4*)g_h)[i] = r;
}

__global__ void k_edge_stats(const void* __restrict__ ei, const float* __restrict__ P,
                             const float* __restrict__ Q, const float* __restrict__ bias,
                             float* __restrict__ sum, float* __restrict__ sq) {
    int lane = threadIdx.x & 31;
    int warp = (blockIdx.x * blockDim.x + threadIdx.x) >> 5;
    int nw = (gridDim.x * blockDim.x) >> 5;
    float4 b = ((const float4*)bias)[lane];
    float4 s = make_float4(0.f, 0.f, 0.f, 0.f);
    float4 s2 = make_float4(0.f, 0.f, 0.f, 0.f);
    int is64 = g_is64;
    for (int e = warp; e < Ee; e += nw) {
        long long si = ld_idx(ei, e, is64);
        long long di = ld_idx(ei, (long long)Ee + e, is64);
        float4 p = ((const float4*)P)[si * 32 + lane];
        float4 q = ((const float4*)Q)[di * 32 + lane];
        float4 z;
        z.x = fmaxf(p.x + q.x + b.x, 0.f);
        z.y = fmaxf(p.y + q.y + b.y, 0.f);
        z.z = fmaxf(p.z + q.z + b.z, 0.f);
        z.w = fmaxf(p.w + q.w + b.w, 0.f);
        s.x += z.x; s.y += z.y; s.z += z.z; s.w += z.w;
        s2.x += z.x * z.x; s2.y += z.y * z.y; s2.z += z.z * z.z; s2.w += z.w * z.w;
    }
    int c = lane * 4;
    atomicAdd(&sum[c + 0], s.x); atomicAdd(&sum[c + 1], s.y);
    atomicAdd(&sum[c + 2], s.z); atomicAdd(&sum[c + 3], s.w);
    atomicAdd(&sq[c + 0], s2.x); atomicAdd(&sq[c + 1], s2.y);
    atomicAdd(&sq[c + 2], s2.z); atomicAdd(&sq[c + 3], s2.w);
}

__global__ void k_bn_pred(const float* gb, const float* beb, const float* W2b, const float* b2b,
                          const float* gc, const float* bec, const float* W2c, const float* b2c) {
    __shared__ float r0s[Hh], r1s[Hh];
    int k = threadIdx.x;
    for (int rel = 0; rel < 2; rel++) {
        const float* g  = rel ? gc  : gb;
        const float* be = rel ? bec : beb;
        const float* W2 = rel ? W2c : W2b;
        const float* b2 = rel ? b2c : b2b;
        const float* sum = &g_stats[256 + rel * 256];
        const float* sq  = &g_stats[256 + rel * 256 + 128];
        float m = sum[k] * (1.0f / Ee);
        float v = sq[k] * (1.0f / Ee) - m * m;
        float a = g[k] * rsqrtf(v + EPSf);
        float cc = be[k] - a * m;
        float w0 = W2[k * 2], w1 = W2[k * 2 + 1];
        g_wp[rel][k * 2] = a * w0;
        g_wp[rel][k * 2 + 1] = a * w1;
        r0s[k] = cc * w0;
        r1s[k] = cc * w1;
        __syncthreads();
        for (int off = 64; off > 0; off >>= 1) {
            if (k < off) { r0s[k] += r0s[k + off]; r1s[k] += r1s[k + off]; }
            __syncthreads();
        }
        if (k == 0) {
            g_bp[rel][0] = r0s[0] + b2[0];
            g_bp[rel][1] = r1s[0] + b2[1];
        }
        __syncthreads();
    }
}

__global__ void k_pred(const void* __restrict__ ei, const float* __restrict__ P,
                       const float* __restrict__ Q, const float* __restrict__ bias,
                       int rel, float* __restrict__ out) {
    int gt = blockIdx.x * blockDim.x + threadIdx.x;
    int e = gt >> 5;
    int lane = gt & 31;
    if (e >= Ee) return;
    int is64 = g_is64;
    float4 b = ((const float4*)bias)[lane];
    const float* W = g_wp[rel];
    float w00 = W[(4 * lane + 0) * 2], w01 = W[(4 * lane + 0) * 2 + 1];
    float w10 = W[(4 * lane + 1) * 2], w11 = W[(4 * lane + 1) * 2 + 1];
    float w20 = W[(4 * lane + 2) * 2], w21 = W[(4 * lane + 2) * 2 + 1];
    float w30 = W[(4 * lane + 3) * 2], w31 = W[(4 * lane + 3) * 2 + 1];
    long long si = ld_idx(ei, e, is64);
    long long di = ld_idx(ei, (long long)Ee + e, is64);
    float4 p = ((const float4*)P)[si * 32 + lane];
    float4 q = ((const float4*)Q)[di * 32 + lane];
    float4 z;
    z.x = fmaxf(p.x + q.x + b.x, 0.f);
    z.y = fmaxf(p.y + q.y + b.y, 0.f);
    z.z = fmaxf(p.z + q.z + b.z, 0.f);
    z.w = fmaxf(p.w + q.w + b.w, 0.f);
    float s0 = z.x * w00 + z.y * w10 + z.z * w20 + z.w * w30;
    float s1 = z.x * w01 + z.y * w11 + z.z * w21 + z.w * w31;
#pragma unroll
    for (int off = 16; off > 0; off >>= 1) {
        s0 += __shfl_xor_sync(0xffffffffu, s0, off);
        s1 += __shfl_xor_sync(0xffffffffu, s1, off);
    }
    if (lane == 0) {
        float2 r = make_float2(s0 + g_bp[rel][0], s1 + g_bp[rel][1]);
        ((float2*)out)[e] = r;
    }
}

__global__ void k_etypes(float* __restrict__ out) {
    int i = blockIdx.x * blockDim.x + threadIdx.x;
    if (i < 2 * Ee) out[i] = (i < Ee) ? 0.f : 1.f;
}

// ---------------- host ----------------
extern "C" void kernel_launch(void* const* d_in, const int* in_sizes, int n_in,
                              void* d_out, int out_size) {
    (void)in_sizes; (void)n_in; (void)out_size;
    const float* x     = (const float*)d_in[0];
    const void*  beam  = d_in[1];
    const void*  col   = d_in[2];
    const float* W_enc = (const float*)d_in[3];
    const float* b_enc = (const float*)d_in[4];
    const float* g_enc = (const float*)d_in[5];
    const float* be_enc= (const float*)d_in[6];
    const float* W1b   = (const float*)d_in[7];
    const float* b1b   = (const float*)d_in[8];
    const float* W1c   = (const float*)d_in[9];
    const float* b1c   = (const float*)d_in[10];
    const float* W2b   = (const float*)d_in[11];
    const float* b2b   = (const float*)d_in[12];
    const float* W2c   = (const float*)d_in[13];
    const float* b2c   = (const float*)d_in[14];
    const float* Wbp1  = (const float*)d_in[15];
    const float* bbp1  = (const float*)d_in[16];
    const float* gbp   = (const float*)d_in[17];
    const float* bebp  = (const float*)d_in[18];
    const float* Wbp2  = (const float*)d_in[19];
    const float* bbp2  = (const float*)d_in[20];
    const float* Wcp1  = (const float*)d_in[21];
    const float* bcp1  = (const float*)d_in[22];
    const float* gcp   = (const float*)d_in[23];
    const float* becp  = (const float*)d_in[24];
    const float* Wcp2  = (const float*)d_in[25];
    const float* bcp2  = (const float*)d_in[26];
    float* out = (float*)d_out;

    float *p_h, *p_xw, *p_agg, *p_pq, *p_dinv, *p_stats;
    cudaGetSymbolAddress((void**)&p_h, g_h);
    cudaGetSymbolAddress((void**)&p_xw, g_xw);
    cudaGetSymbolAddress((void**)&p_agg, g_agg);
    cudaGetSymbolAddress((void**)&p_pq, g_pq);
    cudaGetSymbolAddress((void**)&p_dinv, g_dinv);
    cudaGetSymbolAddress((void**)&p_stats, g_stats);

    cudaFuncSetAttribute(k_mma, cudaFuncAttributeMaxDynamicSharedMemorySize, SMEM_MM);

    const int GB = (Nn + 127) / 128;   // 391 M-tiles
    const int NV4 = Nn * 32;
    const int EV = Ee * 32;

    k_detect<<<1, 256>>>((const int*)beam);
    k_zero<<<(2 * Nn + 255) / 256, 256>>>();
    k_deg<<<(2 * Ee + 255) / 256, 256>>>(beam, col);
    k_dinv<<<(2 * Nn + 255) / 256, 256>>>();

    k_encoder<<<512, 128>>>(x, W_enc, b_enc);
    k_bn_enc<<<1, 128>>>(g_enc, be_enc);
    k_bn_apply<<<(NV4 + 255) / 256, 256>>>();

    // GCN layer 1: both relation GEMMs in one launch
    k_mma<<<dim3(GB, 2), 256, SMEM_MM>>>(p_h, W1b, W1c, W1b, W1b,
                                         p_xw, p_xw + NH, p_xw, p_xw, Nn);
    k_init_agg<<<(NV4 + 255) / 256, 256>>>(b1b, b1c);
    k_scatter<<<(EV + 255) / 256, 256>>>(beam, p_dinv, p_xw, p_agg);
    k_scatter<<<(EV + 255) / 256, 256>>>(col, p_dinv + Nn, p_xw + NH, p_agg + NH);
    k_combine<<<(NV4 + 255) / 256, 256>>>(1);

    // GCN layer 2
    k_mma<<<dim3(GB, 2), 256, SMEM_MM>>>(p_h, W2b, W2c, W2b, W2b,
                                         p_xw, p_xw + NH, p_xw, p_xw, Nn);
    k_init_agg<<<(NV4 + 255) / 256, 256>>>(b2b, b2c);
    k_scatter<<<(EV + 255) / 256, 256>>>(beam, p_dinv, p_xw, p_agg);
    k_scatter<<<(EV + 255) / 256, 256>>>(col, p_dinv + Nn, p_xw + NH, p_agg + NH);
    k_combine<<<(NV4 + 255) / 256, 256>>>(0);

    // edge predictors: P/Q = h2 @ (top/bottom halves of Wbp1 / Wcp1), 4 GEMMs one launch
    k_mma<<<dim3(GB, 4), 256, SMEM_MM>>>(p_h, Wbp1, Wbp1 + Hh * Hh, Wcp1, Wcp1 + Hh * Hh,
                                         p_pq, p_pq + NH, p_pq + 2 * NH, p_pq + 3 * NH, Nn);

    k_edge_stats<<<512, 256>>>(beam, p_pq, p_pq + NH, bbp1, p_stats + 256, p_stats + 384);
    k_edge_stats<<<512, 256>>>(col, p_pq + 2 * NH, p_pq + 3 * NH, bcp1, p_stats + 512, p_stats + 640);
    k_bn_pred<<<1, 128>>>(gbp, bebp, Wbp2, bbp2, gcp, becp, Wcp2, bcp2);

    k_pred<<<(EV + 255) / 256, 256>>>(beam, p_pq, p_pq + NH, bbp1, 0, out);
    k_pred<<<(EV + 255) / 256, 256>>>(col, p_pq + 2 * NH, p_pq + 3 * NH, bcp1, 1, out + 2 * Ee);
    k_etypes<<<(2 * Ee + 255) / 256, 256>>>(out + 4 * Ee);
}